// round 8
// baseline (speedup 1.0000x reference)
#include <cuda_runtime.h>
#include <cstdint>

typedef unsigned long long u64;
typedef unsigned long long ull;
typedef unsigned int u32;

// ============================ problem constants ============================
#define N_   32
#define C_   256
#define H_   56
#define W_   56
#define PH_  58
#define PW_  58
#define PIX_ (H_*W_)                 // 3136
#define M_CNT_ (N_*PIX_)             // 100352
#define NW_  4                       // u64 words per pixel (256 ch)

// ============================ device scratch ============================
__device__ __align__(16) u64 g_Xp1[(size_t)N_*PH_*PW_*NW_];
__device__ __align__(16) u64 g_Xp2[(size_t)N_*PH_*PW_*NW_];
__device__ __align__(16) u64 g_Wp1[9*C_*NW_];
__device__ __align__(16) u64 g_Wp2[9*C_*NW_];
__device__ int  g_c1[9*C_];
__device__ int  g_c2[9*C_];
__device__ __align__(16) short g_S1[(size_t)M_CNT_*C_];
__device__ __align__(16) short g_S2[(size_t)M_CNT_*C_];
__device__ ull g_sum1[C_], g_sq1[C_], g_sum2[C_], g_sq2[C_];
__device__ float g_a1[C_], g_b1[C_], g_a2[C_], g_b2[C_];

// ============================ setup kernels ============================
__global__ void zero_stats_k() {
    int i = threadIdx.x;
    g_sum1[i] = 0ull; g_sq1[i] = 0ull; g_sum2[i] = 0ull; g_sq2[i] = 0ull;
}

__global__ void pack_w_k(const float* __restrict__ w, u64* __restrict__ Wp) {
    int t = blockIdx.x, c = threadIdx.x;
    int ky = t / 3, kx = t % 3;
    #pragma unroll
    for (int j = 0; j < NW_; ++j) {
        u64 bits = 0ull;
        #pragma unroll 4
        for (int cl = 0; cl < 64; ++cl) {
            float v = w[(((size_t)c * C_ + (j * 64 + cl)) * 3 + ky) * 3 + kx];
            bits |= (u64)(v > 0.0f) << cl;
        }
        Wp[((size_t)t * C_ + c) * NW_ + j] = bits;
    }
}

__global__ void corr_w_k(const u64* __restrict__ Wp, int* __restrict__ corr) {
    int c = threadIdx.x;
    int pc[9];
    #pragma unroll
    for (int t = 0; t < 9; ++t) {
        int s = 0;
        #pragma unroll
        for (int j = 0; j < NW_; ++j) s += __popcll(Wp[((size_t)t * C_ + c) * NW_ + j]);
        pc[t] = s;
    }
    for (int type = 0; type < 9; ++type) {
        int rt = type / 3, ct = type % 3;
        int s = 0;
        #pragma unroll
        for (int ky = 0; ky < 3; ++ky)
            #pragma unroll
            for (int kx = 0; kx < 3; ++kx) {
                bool rinv = (rt == 0 && ky == 0) || (rt == 2 && ky == 2);
                bool cinv = (ct == 0 && kx == 0) || (ct == 2 && kx == 2);
                if (rinv || cinv) s += 256 - 2 * pc[ky * 3 + kx];
            }
        corr[type * C_ + c] = s;
    }
}

__global__ void pack_x_k(const float* __restrict__ x, u64* __restrict__ Xp) {
    int px = threadIdx.x, j = threadIdx.y;
    int py = blockIdx.x, n = blockIdx.y;
    size_t oidx = (((size_t)n * PH_ + py) * PW_ + px) * NW_ + j;
    if (px == 0 || px == PW_ - 1 || py == 0 || py == PH_ - 1) { Xp[oidx] = 0ull; return; }
    const float* xp = x + (((size_t)n * C_ + j * 64) * H_ + (py - 1)) * W_ + (px - 1);
    u64 bits = 0ull;
    #pragma unroll 8
    for (int cl = 0; cl < 64; ++cl)
        bits |= (u64)(xp[(size_t)cl * PIX_] > 0.0f) << cl;
    Xp[oidx] = bits;
}

// ============================ Harley-Seal carry-save popcount ============================
struct HS { u32 on, tw, fo, ei, si, c2, c4, c8, c16, c32; };

__device__ __forceinline__ u32 maj3(u32 a, u32 b, u32 c) { return (a & b) | (c & (a | b)); }

// push one pair of words (full adder streaming); PC = pair index 0..17 (compile-time)
template<int PC>
__device__ __forceinline__ void hs_pair(HS& s, u32 a, u32 b) {
    u32 c1 = maj3(s.on, a, b);
    s.on ^= a ^ b;
    if constexpr (PC & 1) {
        u32 c2n = maj3(s.tw, s.c2, c1); s.tw ^= s.c2 ^ c1;
        if constexpr ((PC >> 1) & 1) {
            u32 c4n = maj3(s.fo, s.c4, c2n); s.fo ^= s.c4 ^ c2n;
            if constexpr ((PC >> 2) & 1) {
                u32 c8n = maj3(s.ei, s.c8, c4n); s.ei ^= s.c8 ^ c4n;
                if constexpr ((PC >> 3) & 1) {
                    u32 c16n = maj3(s.si, s.c16, c8n); s.si ^= s.c16 ^ c8n;
                    s.c32 = c16n;
                } else s.c16 = c8n;
            } else s.c8 = c4n;
        } else s.c4 = c2n;
    } else s.c2 = c1;
}
// after 18 pairs: valid words = on(1) tw(2) fo(4) c4(4, leftover from P4=8) ei(8) si(16) c32(32)
__device__ __forceinline__ int hs_final(const HS& s) {
    return __popc(s.on) + 2 * __popc(s.tw) + 4 * (__popc(s.fo) + __popc(s.c4))
         + 8 * __popc(s.ei) + 16 * __popc(s.si) + 32 * __popc(s.c32);
}

// ============================ hot kernel: CSA XNOR-popcount conv ============================
// thread = (cout, half-of-256-cin); 2 output pixels per iteration; HS compression.
#define PAIRS_KY(KY) { \
    const u64* rp = &sx[((KY) * PW_ + ox) * NW_ + half2]; \
    const uint4 x0 = *(const uint4*)(rp); \
    const uint4 x1 = *(const uint4*)(rp + NW_); \
    const uint4 x2 = *(const uint4*)(rp + 2 * NW_); \
    const uint4 x3 = *(const uint4*)(rp + 3 * NW_); \
    hs_pair<(KY)*6+0>(h0, x0.x ^ w[(KY)*3+0].x, x0.y ^ w[(KY)*3+0].y); \
    hs_pair<(KY)*6+1>(h0, x0.z ^ w[(KY)*3+0].z, x0.w ^ w[(KY)*3+0].w); \
    hs_pair<(KY)*6+0>(h1, x1.x ^ w[(KY)*3+0].x, x1.y ^ w[(KY)*3+0].y); \
    hs_pair<(KY)*6+1>(h1, x1.z ^ w[(KY)*3+0].z, x1.w ^ w[(KY)*3+0].w); \
    hs_pair<(KY)*6+2>(h0, x1.x ^ w[(KY)*3+1].x, x1.y ^ w[(KY)*3+1].y); \
    hs_pair<(KY)*6+3>(h0, x1.z ^ w[(KY)*3+1].z, x1.w ^ w[(KY)*3+1].w); \
    hs_pair<(KY)*6+2>(h1, x2.x ^ w[(KY)*3+1].x, x2.y ^ w[(KY)*3+1].y); \
    hs_pair<(KY)*6+3>(h1, x2.z ^ w[(KY)*3+1].z, x2.w ^ w[(KY)*3+1].w); \
    hs_pair<(KY)*6+4>(h0, x2.x ^ w[(KY)*3+2].x, x2.y ^ w[(KY)*3+2].y); \
    hs_pair<(KY)*6+5>(h0, x2.z ^ w[(KY)*3+2].z, x2.w ^ w[(KY)*3+2].w); \
    hs_pair<(KY)*6+4>(h1, x3.x ^ w[(KY)*3+2].x, x3.y ^ w[(KY)*3+2].y); \
    hs_pair<(KY)*6+5>(h1, x3.z ^ w[(KY)*3+2].z, x3.w ^ w[(KY)*3+2].w); \
}

__global__ __launch_bounds__(256, 2)
void conv_pop_k(const u64* __restrict__ Xp,
                const u64* __restrict__ Wp,
                const int* __restrict__ corr,
                short* __restrict__ S,
                ull* __restrict__ sum, ull* __restrict__ sq)
{
    __shared__ u64 sx[3 * PW_ * NW_];     // 5568 B
    const int t     = threadIdx.x;
    const int half  = t & 1;
    const int half2 = half * 2;
    const int c     = blockIdx.z * 128 + (t >> 1);
    const int oy    = blockIdx.x;
    const int n     = blockIdx.y;

    uint4 w[9];
    #pragma unroll
    for (int tp = 0; tp < 9; ++tp)
        w[tp] = *(const uint4*)&Wp[((size_t)tp * C_ + c) * NW_ + half2];

    const int rt = (oy == 0) ? 0 : ((oy == H_ - 1) ? 2 : 1);
    const int cL = corr[(rt * 3 + 0) * C_ + c];
    const int cM = corr[(rt * 3 + 1) * C_ + c];
    const int cR = corr[(rt * 3 + 2) * C_ + c];

    {
        const ulonglong2* src = (const ulonglong2*)(Xp + (((size_t)n * PH_ + oy) * PW_) * NW_);
        ulonglong2* dst = (ulonglong2*)sx;
        for (int i = t; i < 3 * PW_ * NW_ / 2; i += 256) dst[i] = src[i];
    }
    __syncthreads();

    int ss = 0, qq = 0;
    const size_t rowbase = (((size_t)n * H_ + oy) * W_) * C_ + c;

    #pragma unroll 1
    for (int ox = 0; ox < W_; ox += 2) {
        HS h0 = {0,0,0,0,0,0,0,0,0,0};
        HS h1 = {0,0,0,0,0,0,0,0,0,0};
        PAIRS_KY(0)
        PAIRS_KY(1)
        PAIRS_KY(2)
        const int acc0 = hs_final(h0);    // <= 1152
        const int acc1 = hs_final(h1);
        // merge halves: both pixels packed, one shfl
        const unsigned p01 = (unsigned)acc0 | ((unsigned)acc1 << 16);
        const unsigned f01 = p01 + __shfl_xor_sync(0xffffffffu, p01, 1);
        // even thread -> pixel ox (low), odd -> pixel ox+1 (high)
        const int gx = ox + half;
        const int f  = half ? (int)(f01 >> 16) : (int)(f01 & 0xffffu);
        const int cc = (gx == 0) ? cL : ((gx == W_ - 1) ? cR : cM);
        const int sv = 2304 - 2 * f - cc;
        S[rowbase + (size_t)gx * C_] = (short)sv;
        ss += sv;
        qq += sv * sv;
    }
    atomicAdd(&sum[c], (ull)(long long)ss);
    atomicAdd(&sq[c],  (ull)(long long)qq);
}

// ============================ bn / thresh / final ============================
__global__ void bnparams_k(const ull* __restrict__ sum, const ull* __restrict__ sq,
                           const float* __restrict__ gamma, const float* __restrict__ beta,
                           float* __restrict__ a, float* __restrict__ b) {
    int c = threadIdx.x;
    const double M = (double)M_CNT_;
    double mS = (double)(long long)sum[c] / M;
    double vS = (double)(long long)sq[c] / M - mS * mS;
    double m = 0.5 * mS;
    double v = 0.25 * vS;
    double r = 1.0 / sqrt(v + 1e-5);
    double g = (double)gamma[c];
    a[c] = (float)(0.5 * r * g);
    b[c] = (float)((double)beta[c] - m * r * g);
}

__global__ void thresh_ballot_k(const short* __restrict__ S,
                                const float* __restrict__ a, const float* __restrict__ b,
                                u64* __restrict__ Xp2) {
    int c = threadIdx.x;
    int py = blockIdx.x, n = blockIdx.y;
    int warp = c >> 5, lane = c & 31;
    float av = a[c], bv = b[c];
    bool rowv = (py >= 1 && py <= H_);
    for (int px = 0; px < PW_; ++px) {
        unsigned bit = 0u;
        if (rowv && px >= 1 && px <= W_) {
            int v = S[(((size_t)n * H_ + (py - 1)) * W_ + (px - 1)) * C_ + c];
            bit = (av * (float)v + bv > 0.0f) ? 1u : 0u;
        }
        unsigned m = __ballot_sync(0xffffffffu, bit);
        if (lane == 0)
            ((unsigned*)(Xp2 + (((size_t)n * PH_ + py) * PW_ + px) * NW_))[warp] = m;
    }
}

__global__ __launch_bounds__(256)
void final_k(const short* __restrict__ S2,
             const float* __restrict__ a, const float* __restrict__ b,
             const float* __restrict__ x, float* __restrict__ out) {
    __shared__ short tile[32][33];
    int n = blockIdx.z, pt = blockIdx.x, ct = blockIdx.y;
    int tx = threadIdx.x, ty = threadIdx.y;
    #pragma unroll
    for (int i = 0; i < 4; ++i) {
        int rl = ty + i * 8;
        tile[rl][tx] = S2[((size_t)n * PIX_ + pt * 32 + rl) * C_ + ct * 32 + tx];
    }
    __syncthreads();
    int p = pt * 32 + tx;
    int py = p / W_, px = p % W_;
    #pragma unroll
    for (int i = 0; i < 4; ++i) {
        int cl = ty + i * 8;
        int cc = ct * 32 + cl;
        size_t oi = (((size_t)n * C_ + cc) * H_ + py) * W_ + px;
        float v = a[cc] * (float)tile[tx][cl] + b[cc] + x[oi];
        out[oi] = fminf(1.0f, fmaxf(-1.0f, v));
    }
}

// ============================ launch ============================
extern "C" void kernel_launch(void* const* d_in, const int* in_sizes, int n_in,
                              void* d_out, int out_size) {
    const float* x  = (const float*)d_in[0];
    const float* w1 = (const float*)d_in[1];
    const float* g1 = (const float*)d_in[2];
    const float* b1 = (const float*)d_in[3];
    const float* w2 = (const float*)d_in[4];
    const float* g2 = (const float*)d_in[5];
    const float* b2 = (const float*)d_in[6];
    float* out = (float*)d_out;

    void *pX1, *pX2, *pW1, *pW2, *pc1, *pc2, *pS1, *pS2;
    void *psum1, *psq1, *psum2, *psq2, *pa1, *pb1, *pa2, *pb2;
    cudaGetSymbolAddress(&pX1, g_Xp1);  cudaGetSymbolAddress(&pX2, g_Xp2);
    cudaGetSymbolAddress(&pW1, g_Wp1);  cudaGetSymbolAddress(&pW2, g_Wp2);
    cudaGetSymbolAddress(&pc1, g_c1);   cudaGetSymbolAddress(&pc2, g_c2);
    cudaGetSymbolAddress(&pS1, g_S1);   cudaGetSymbolAddress(&pS2, g_S2);
    cudaGetSymbolAddress(&psum1, g_sum1); cudaGetSymbolAddress(&psq1, g_sq1);
    cudaGetSymbolAddress(&psum2, g_sum2); cudaGetSymbolAddress(&psq2, g_sq2);
    cudaGetSymbolAddress(&pa1, g_a1);   cudaGetSymbolAddress(&pb1, g_b1);
    cudaGetSymbolAddress(&pa2, g_a2);   cudaGetSymbolAddress(&pb2, g_b2);

    pack_w_k<<<9, 256>>>(w1, (u64*)pW1);
    pack_w_k<<<9, 256>>>(w2, (u64*)pW2);
    corr_w_k<<<1, 256>>>((const u64*)pW1, (int*)pc1);
    corr_w_k<<<1, 256>>>((const u64*)pW2, (int*)pc2);
    zero_stats_k<<<1, 256>>>();
    pack_x_k<<<dim3(PH_, N_), dim3(PW_, NW_)>>>(x, (u64*)pX1);

    conv_pop_k<<<dim3(H_, N_, 2), 256>>>((const u64*)pX1, (const u64*)pW1,
                                         (const int*)pc1, (short*)pS1,
                                         (ull*)psum1, (ull*)psq1);
    bnparams_k<<<1, 256>>>((const ull*)psum1, (const ull*)psq1, g1, b1,
                           (float*)pa1, (float*)pb1);
    thresh_ballot_k<<<dim3(PH_, N_), 256>>>((const short*)pS1,
        (const float*)pa1, (const float*)pb1, (u64*)pX2);

    conv_pop_k<<<dim3(H_, N_, 2), 256>>>((const u64*)pX2, (const u64*)pW2,
                                         (const int*)pc2, (short*)pS2,
                                         (ull*)psum2, (ull*)psq2);
    bnparams_k<<<1, 256>>>((const ull*)psum2, (const ull*)psq2, g2, b2,
                           (float*)pa2, (float*)pb2);

    final_k<<<dim3(PIX_ / 32, 8, N_), dim3(32, 8)>>>(
        (const short*)pS2, (const float*)pa2, (const float*)pb2, x, out);
}

// round 9
// speedup vs baseline: 1.1885x; 1.1885x over previous
#include <cuda_runtime.h>
#include <cstdint>

typedef unsigned long long u64;
typedef unsigned long long ull;
typedef unsigned int u32;

// ============================ problem constants ============================
#define N_   32
#define C_   256
#define H_   56
#define W_   56
#define PH_  58
#define PW_  58
#define PIX_ (H_*W_)                 // 3136
#define M_CNT_ (N_*PIX_)             // 100352
#define NW_  4                       // u64 words per pixel (256 ch)

// ============================ device scratch ============================
__device__ __align__(16) u64 g_Xp1[(size_t)N_*PH_*PW_*NW_];
__device__ __align__(16) u64 g_Xp2[(size_t)N_*PH_*PW_*NW_];
__device__ __align__(16) u64 g_Wp1[9*C_*NW_];
__device__ __align__(16) u64 g_Wp2[9*C_*NW_];
__device__ int  g_c1[9*C_];
__device__ int  g_c2[9*C_];
__device__ __align__(16) short g_S1[(size_t)M_CNT_*C_];
__device__ __align__(16) short g_S2[(size_t)M_CNT_*C_];
__device__ ull g_sum1[C_], g_sq1[C_], g_sum2[C_], g_sq2[C_];
__device__ float g_a1[C_], g_b1[C_], g_a2[C_], g_b2[C_];

// ============================ setup kernels ============================
// pack weights; optionally zero the BN stat accumulators (first launch only)
__global__ void pack_w_k(const float* __restrict__ w, u64* __restrict__ Wp, int zero_stats) {
    int t = blockIdx.x, c = threadIdx.x;
    if (zero_stats && t == 0) {
        g_sum1[c] = 0ull; g_sq1[c] = 0ull; g_sum2[c] = 0ull; g_sq2[c] = 0ull;
    }
    int ky = t / 3, kx = t % 3;
    #pragma unroll
    for (int j = 0; j < NW_; ++j) {
        u64 bits = 0ull;
        #pragma unroll 4
        for (int cl = 0; cl < 64; ++cl) {
            float v = w[(((size_t)c * C_ + (j * 64 + cl)) * 3 + ky) * 3 + kx];
            bits |= (u64)(v > 0.0f) << cl;
        }
        Wp[((size_t)t * C_ + c) * NW_ + j] = bits;
    }
}

__global__ void corr_w_k(const u64* __restrict__ Wp, int* __restrict__ corr) {
    int c = threadIdx.x;
    int pc[9];
    #pragma unroll
    for (int t = 0; t < 9; ++t) {
        int s = 0;
        #pragma unroll
        for (int j = 0; j < NW_; ++j) s += __popcll(Wp[((size_t)t * C_ + c) * NW_ + j]);
        pc[t] = s;
    }
    for (int type = 0; type < 9; ++type) {
        int rt = type / 3, ct = type % 3;
        int s = 0;
        #pragma unroll
        for (int ky = 0; ky < 3; ++ky)
            #pragma unroll
            for (int kx = 0; kx < 3; ++kx) {
                bool rinv = (rt == 0 && ky == 0) || (rt == 2 && ky == 2);
                bool cinv = (ct == 0 && kx == 0) || (ct == 2 && kx == 2);
                if (rinv || cinv) s += 256 - 2 * pc[ky * 3 + kx];
            }
        corr[type * C_ + c] = s;
    }
}

__global__ void pack_x_k(const float* __restrict__ x, u64* __restrict__ Xp) {
    int px = threadIdx.x, j = threadIdx.y;
    int py = blockIdx.x, n = blockIdx.y;
    size_t oidx = (((size_t)n * PH_ + py) * PW_ + px) * NW_ + j;
    if (px == 0 || px == PW_ - 1 || py == 0 || py == PH_ - 1) { Xp[oidx] = 0ull; return; }
    const float* xp = x + (((size_t)n * C_ + j * 64) * H_ + (py - 1)) * W_ + (px - 1);
    u64 bits = 0ull;
    #pragma unroll 8
    for (int cl = 0; cl < 64; ++cl)
        bits |= (u64)(xp[(size_t)cl * PIX_] > 0.0f) << cl;
    Xp[oidx] = bits;
}

// ============================ forced-LOP3 Harley-Seal ============================
__device__ __forceinline__ u32 xor3(u32 a, u32 b, u32 c) {
    u32 d; asm("lop3.b32 %0,%1,%2,%3,0x96;" : "=r"(d) : "r"(a), "r"(b), "r"(c)); return d;
}
__device__ __forceinline__ u32 maj3(u32 a, u32 b, u32 c) {
    u32 d; asm("lop3.b32 %0,%1,%2,%3,0xE8;" : "=r"(d) : "r"(a), "r"(b), "r"(c)); return d;
}

struct HS { u32 on, tw, fo, ei, si, c2, c4, c8, c16, c32; };

// push one pair of words; PC = pair index 0..17 (compile-time)
template<int PC>
__device__ __forceinline__ void hs_pair(HS& s, u32 a, u32 b) {
    u32 c1 = maj3(s.on, a, b);
    s.on = xor3(s.on, a, b);
    if constexpr (PC & 1) {
        u32 c2n = maj3(s.tw, s.c2, c1); s.tw = xor3(s.tw, s.c2, c1);
        if constexpr ((PC >> 1) & 1) {
            u32 c4n = maj3(s.fo, s.c4, c2n); s.fo = xor3(s.fo, s.c4, c2n);
            if constexpr ((PC >> 2) & 1) {
                u32 c8n = maj3(s.ei, s.c8, c4n); s.ei = xor3(s.ei, s.c8, c4n);
                if constexpr ((PC >> 3) & 1) {
                    u32 c16n = maj3(s.si, s.c16, c8n); s.si = xor3(s.si, s.c16, c8n);
                    s.c32 = c16n;
                } else s.c16 = c8n;
            } else s.c8 = c4n;
        } else s.c4 = c2n;
    } else s.c2 = c1;
}
// after 18 pairs: on(w1) tw(w2) fo(w4) c4(w4 leftover) ei(w8) si(w16) c32(w32)
__device__ __forceinline__ int hs_final(const HS& s) {
    return __popc(s.on) + 2 * __popc(s.tw) + 4 * (__popc(s.fo) + __popc(s.c4))
         + 8 * __popc(s.ei) + 16 * __popc(s.si) + 32 * __popc(s.c32);
}

// ============================ hot kernel: CSA XNOR-popcount conv ============================
#define PAIRS_KY(KY) { \
    const u64* rp = &sx[((KY) * PW_ + ox) * NW_ + half2]; \
    const uint4 x0 = *(const uint4*)(rp); \
    const uint4 x1 = *(const uint4*)(rp + NW_); \
    const uint4 x2 = *(const uint4*)(rp + 2 * NW_); \
    const uint4 x3 = *(const uint4*)(rp + 3 * NW_); \
    hs_pair<(KY)*6+0>(h0, x0.x ^ w[(KY)*3+0].x, x0.y ^ w[(KY)*3+0].y); \
    hs_pair<(KY)*6+1>(h0, x0.z ^ w[(KY)*3+0].z, x0.w ^ w[(KY)*3+0].w); \
    hs_pair<(KY)*6+0>(h1, x1.x ^ w[(KY)*3+0].x, x1.y ^ w[(KY)*3+0].y); \
    hs_pair<(KY)*6+1>(h1, x1.z ^ w[(KY)*3+0].z, x1.w ^ w[(KY)*3+0].w); \
    hs_pair<(KY)*6+2>(h0, x1.x ^ w[(KY)*3+1].x, x1.y ^ w[(KY)*3+1].y); \
    hs_pair<(KY)*6+3>(h0, x1.z ^ w[(KY)*3+1].z, x1.w ^ w[(KY)*3+1].w); \
    hs_pair<(KY)*6+2>(h1, x2.x ^ w[(KY)*3+1].x, x2.y ^ w[(KY)*3+1].y); \
    hs_pair<(KY)*6+3>(h1, x2.z ^ w[(KY)*3+1].z, x2.w ^ w[(KY)*3+1].w); \
    hs_pair<(KY)*6+4>(h0, x2.x ^ w[(KY)*3+2].x, x2.y ^ w[(KY)*3+2].y); \
    hs_pair<(KY)*6+5>(h0, x2.z ^ w[(KY)*3+2].z, x2.w ^ w[(KY)*3+2].w); \
    hs_pair<(KY)*6+4>(h1, x3.x ^ w[(KY)*3+2].x, x3.y ^ w[(KY)*3+2].y); \
    hs_pair<(KY)*6+5>(h1, x3.z ^ w[(KY)*3+2].z, x3.w ^ w[(KY)*3+2].w); \
}

__global__ __launch_bounds__(256, 2)
void conv_pop_k(const u64* __restrict__ Xp,
                const u64* __restrict__ Wp,
                const int* __restrict__ corr,
                short* __restrict__ S,
                ull* __restrict__ sum, ull* __restrict__ sq)
{
    __shared__ u64 sx[3 * PW_ * NW_];     // 5568 B
    const int t     = threadIdx.x;
    const int half  = t & 1;
    const int half2 = half * 2;
    const int c     = blockIdx.z * 128 + (t >> 1);
    const int oy    = blockIdx.x;
    const int n     = blockIdx.y;

    uint4 w[9];
    #pragma unroll
    for (int tp = 0; tp < 9; ++tp)
        w[tp] = *(const uint4*)&Wp[((size_t)tp * C_ + c) * NW_ + half2];

    const int rt = (oy == 0) ? 0 : ((oy == H_ - 1) ? 2 : 1);
    const int cL = corr[(rt * 3 + 0) * C_ + c];
    const int cM = corr[(rt * 3 + 1) * C_ + c];
    const int cR = corr[(rt * 3 + 2) * C_ + c];

    {
        const ulonglong2* src = (const ulonglong2*)(Xp + (((size_t)n * PH_ + oy) * PW_) * NW_);
        ulonglong2* dst = (ulonglong2*)sx;
        for (int i = t; i < 3 * PW_ * NW_ / 2; i += 256) dst[i] = src[i];
    }
    __syncthreads();

    int ss = 0, qq = 0;
    const size_t rowbase = (((size_t)n * H_ + oy) * W_) * C_ + c;

    #pragma unroll 1
    for (int ox = 0; ox < W_; ox += 2) {
        HS h0 = {0,0,0,0,0,0,0,0,0,0};
        HS h1 = {0,0,0,0,0,0,0,0,0,0};
        PAIRS_KY(0)
        PAIRS_KY(1)
        PAIRS_KY(2)
        const int acc0 = hs_final(h0);
        const int acc1 = hs_final(h1);
        const unsigned p01 = (unsigned)acc0 | ((unsigned)acc1 << 16);
        const unsigned f01 = p01 + __shfl_xor_sync(0xffffffffu, p01, 1);
        const int gx = ox + half;
        const int f  = half ? (int)(f01 >> 16) : (int)(f01 & 0xffffu);
        const int cc = (gx == 0) ? cL : ((gx == W_ - 1) ? cR : cM);
        const int sv = 2304 - 2 * f - cc;
        S[rowbase + (size_t)gx * C_] = (short)sv;
        ss += sv;
        qq += sv * sv;
    }
    atomicAdd(&sum[c], (ull)(long long)ss);
    atomicAdd(&sq[c],  (ull)(long long)qq);
}

// ============================ bn / thresh / final ============================
__global__ void bnparams_k(const ull* __restrict__ sum, const ull* __restrict__ sq,
                           const float* __restrict__ gamma, const float* __restrict__ beta,
                           float* __restrict__ a, float* __restrict__ b) {
    int c = threadIdx.x;
    const double M = (double)M_CNT_;
    double mS = (double)(long long)sum[c] / M;
    double vS = (double)(long long)sq[c] / M - mS * mS;
    double m = 0.5 * mS;
    double v = 0.25 * vS;
    double r = 1.0 / sqrt(v + 1e-5);
    double g = (double)gamma[c];
    a[c] = (float)(0.5 * r * g);
    b[c] = (float)((double)beta[c] - m * r * g);
}

__global__ void thresh_ballot_k(const short* __restrict__ S,
                                const float* __restrict__ a, const float* __restrict__ b,
                                u64* __restrict__ Xp2) {
    int c = threadIdx.x;
    int py = blockIdx.x, n = blockIdx.y;
    int warp = c >> 5, lane = c & 31;
    float av = a[c], bv = b[c];
    bool rowv = (py >= 1 && py <= H_);
    for (int px = 0; px < PW_; ++px) {
        unsigned bit = 0u;
        if (rowv && px >= 1 && px <= W_) {
            int v = S[(((size_t)n * H_ + (py - 1)) * W_ + (px - 1)) * C_ + c];
            bit = (av * (float)v + bv > 0.0f) ? 1u : 0u;
        }
        unsigned m = __ballot_sync(0xffffffffu, bit);
        if (lane == 0)
            ((unsigned*)(Xp2 + (((size_t)n * PH_ + py) * PW_ + px) * NW_))[warp] = m;
    }
}

__global__ __launch_bounds__(256)
void final_k(const short* __restrict__ S2,
             const float* __restrict__ a, const float* __restrict__ b,
             const float* __restrict__ x, float* __restrict__ out) {
    __shared__ short tile[32][33];
    int n = blockIdx.z, pt = blockIdx.x, ct = blockIdx.y;
    int tx = threadIdx.x, ty = threadIdx.y;
    #pragma unroll
    for (int i = 0; i < 4; ++i) {
        int rl = ty + i * 8;
        tile[rl][tx] = S2[((size_t)n * PIX_ + pt * 32 + rl) * C_ + ct * 32 + tx];
    }
    __syncthreads();
    int p = pt * 32 + tx;
    int py = p / W_, px = p % W_;
    #pragma unroll
    for (int i = 0; i < 4; ++i) {
        int cl = ty + i * 8;
        int cc = ct * 32 + cl;
        size_t oi = (((size_t)n * C_ + cc) * H_ + py) * W_ + px;
        float v = a[cc] * (float)tile[tx][cl] + b[cc] + x[oi];
        out[oi] = fminf(1.0f, fmaxf(-1.0f, v));
    }
}

// ============================ launch ============================
extern "C" void kernel_launch(void* const* d_in, const int* in_sizes, int n_in,
                              void* d_out, int out_size) {
    const float* x  = (const float*)d_in[0];
    const float* w1 = (const float*)d_in[1];
    const float* g1 = (const float*)d_in[2];
    const float* b1 = (const float*)d_in[3];
    const float* w2 = (const float*)d_in[4];
    const float* g2 = (const float*)d_in[5];
    const float* b2 = (const float*)d_in[6];
    float* out = (float*)d_out;

    void *pX1, *pX2, *pW1, *pW2, *pc1, *pc2, *pS1, *pS2;
    void *psum1, *psq1, *psum2, *psq2, *pa1, *pb1, *pa2, *pb2;
    cudaGetSymbolAddress(&pX1, g_Xp1);  cudaGetSymbolAddress(&pX2, g_Xp2);
    cudaGetSymbolAddress(&pW1, g_Wp1);  cudaGetSymbolAddress(&pW2, g_Wp2);
    cudaGetSymbolAddress(&pc1, g_c1);   cudaGetSymbolAddress(&pc2, g_c2);
    cudaGetSymbolAddress(&pS1, g_S1);   cudaGetSymbolAddress(&pS2, g_S2);
    cudaGetSymbolAddress(&psum1, g_sum1); cudaGetSymbolAddress(&psq1, g_sq1);
    cudaGetSymbolAddress(&psum2, g_sum2); cudaGetSymbolAddress(&psq2, g_sq2);
    cudaGetSymbolAddress(&pa1, g_a1);   cudaGetSymbolAddress(&pb1, g_b1);
    cudaGetSymbolAddress(&pa2, g_a2);   cudaGetSymbolAddress(&pb2, g_b2);

    // launch order chosen so conv1 is launch #3 (the one ncu profiles)
    pack_w_k<<<9, 256>>>(w1, (u64*)pW1, 1);                         // #0 (also zeros stats)
    corr_w_k<<<1, 256>>>((const u64*)pW1, (int*)pc1);               // #1
    pack_x_k<<<dim3(PH_, N_), dim3(PW_, NW_)>>>(x, (u64*)pX1);      // #2
    conv_pop_k<<<dim3(H_, N_, 2), 256>>>((const u64*)pX1, (const u64*)pW1,   // #3
                                         (const int*)pc1, (short*)pS1,
                                         (ull*)psum1, (ull*)psq1);
    pack_w_k<<<9, 256>>>(w2, (u64*)pW2, 0);                         // #4
    corr_w_k<<<1, 256>>>((const u64*)pW2, (int*)pc2);               // #5
    bnparams_k<<<1, 256>>>((const ull*)psum1, (const ull*)psq1, g1, b1,
                           (float*)pa1, (float*)pb1);               // #6
    thresh_ballot_k<<<dim3(PH_, N_), 256>>>((const short*)pS1,
        (const float*)pa1, (const float*)pb1, (u64*)pX2);           // #7
    conv_pop_k<<<dim3(H_, N_, 2), 256>>>((const u64*)pX2, (const u64*)pW2,   // #8
                                         (const int*)pc2, (short*)pS2,
                                         (ull*)psum2, (ull*)psq2);
    bnparams_k<<<1, 256>>>((const ull*)psum2, (const ull*)psq2, g2, b2,
                           (float*)pa2, (float*)pb2);               // #9
    final_k<<<dim3(PIX_ / 32, 8, N_), dim3(32, 8)>>>(
        (const short*)pS2, (const float*)pa2, (const float*)pb2, x, out);   // #10
}

// round 10
// speedup vs baseline: 1.4144x; 1.1901x over previous
#include <cuda_runtime.h>
#include <cstdint>

typedef unsigned long long u64;
typedef unsigned long long ull;
typedef unsigned int u32;

// ============================ problem constants ============================
#define N_   32
#define C_   256
#define H_   56
#define W_   56
#define PH_  58
#define PW_  58
#define PIX_ (H_*W_)                 // 3136
#define M_CNT_ (N_*PIX_)             // 100352
#define NW_  4                       // u64 words per pixel (256 ch)

// ============================ device scratch ============================
__device__ __align__(16) u64 g_Xp1[(size_t)N_*PH_*PW_*NW_];
__device__ __align__(16) u64 g_Xp2[(size_t)N_*PH_*PW_*NW_];
__device__ __align__(16) u64 g_Wp1[9*C_*NW_];
__device__ __align__(16) u64 g_Wp2[9*C_*NW_];
__device__ int  g_c1[9*C_];
__device__ int  g_c2[9*C_];
__device__ __align__(16) short g_S1[(size_t)M_CNT_*C_];
__device__ __align__(16) short g_S2[(size_t)M_CNT_*C_];
__device__ ull g_sum1[C_], g_sq1[C_], g_sum2[C_], g_sq2[C_];
__device__ float g_a1[C_], g_b1[C_], g_a2[C_], g_b2[C_];

// ============================ setup kernels ============================
__global__ void pack_w_k(const float* __restrict__ w, u64* __restrict__ Wp, int zero_stats) {
    int t = blockIdx.x, c = threadIdx.x;
    if (zero_stats && t == 0) {
        g_sum1[c] = 0ull; g_sq1[c] = 0ull; g_sum2[c] = 0ull; g_sq2[c] = 0ull;
    }
    int ky = t / 3, kx = t % 3;
    #pragma unroll
    for (int j = 0; j < NW_; ++j) {
        u64 bits = 0ull;
        #pragma unroll 4
        for (int cl = 0; cl < 64; ++cl) {
            float v = w[(((size_t)c * C_ + (j * 64 + cl)) * 3 + ky) * 3 + kx];
            bits |= (u64)(v > 0.0f) << cl;
        }
        Wp[((size_t)t * C_ + c) * NW_ + j] = bits;
    }
}

__global__ void corr_w_k(const u64* __restrict__ Wp, int* __restrict__ corr) {
    int c = threadIdx.x;
    int pc[9];
    #pragma unroll
    for (int t = 0; t < 9; ++t) {
        int s = 0;
        #pragma unroll
        for (int j = 0; j < NW_; ++j) s += __popcll(Wp[((size_t)t * C_ + c) * NW_ + j]);
        pc[t] = s;
    }
    for (int type = 0; type < 9; ++type) {
        int rt = type / 3, ct = type % 3;
        int s = 0;
        #pragma unroll
        for (int ky = 0; ky < 3; ++ky)
            #pragma unroll
            for (int kx = 0; kx < 3; ++kx) {
                bool rinv = (rt == 0 && ky == 0) || (rt == 2 && ky == 2);
                bool cinv = (ct == 0 && kx == 0) || (ct == 2 && kx == 2);
                if (rinv || cinv) s += 256 - 2 * pc[ky * 3 + kx];
            }
        corr[type * C_ + c] = s;
    }
}

__global__ void pack_x_k(const float* __restrict__ x, u64* __restrict__ Xp) {
    int px = threadIdx.x, j = threadIdx.y;
    int py = blockIdx.x, n = blockIdx.y;
    size_t oidx = (((size_t)n * PH_ + py) * PW_ + px) * NW_ + j;
    if (px == 0 || px == PW_ - 1 || py == 0 || py == PH_ - 1) { Xp[oidx] = 0ull; return; }
    const float* xp = x + (((size_t)n * C_ + j * 64) * H_ + (py - 1)) * W_ + (px - 1);
    u64 bits = 0ull;
    #pragma unroll 8
    for (int cl = 0; cl < 64; ++cl)
        bits |= (u64)(xp[(size_t)cl * PIX_] > 0.0f) << cl;
    Xp[oidx] = bits;
}

// ============================ shallow CSA primitives ============================
__device__ __forceinline__ u32 xor3(u32 a, u32 b, u32 c) {
    u32 d; asm("lop3.b32 %0,%1,%2,%3,0x96;" : "=r"(d) : "r"(a), "r"(b), "r"(c)); return d;
}
__device__ __forceinline__ u32 maj3(u32 a, u32 b, u32 c) {
    u32 d; asm("lop3.b32 %0,%1,%2,%3,0xE8;" : "=r"(d) : "r"(a), "r"(b), "r"(c)); return d;
}
// full-adder step at ones level only: carry popcounted immediately (popc pipe),
// weighted accumulate on the fma pipe via IMAD.
__device__ __forceinline__ void fa2(u32& on, int& acc, u32 a, u32 b) {
    u32 c1 = maj3(on, a, b);
    on = xor3(on, a, b);
    int pc = __popc(c1);
    asm("mad.lo.s32 %0, %1, 2, %0;" : "+r"(acc) : "r"(pc));
}

// ============================ hot kernel: balanced-pipe XNOR conv ============================
#define PAIRS_KY(KY) { \
    const u64* rp = &sx[((KY) * PW_ + ox) * NW_ + half2]; \
    const uint4 x0 = *(const uint4*)(rp); \
    const uint4 x1 = *(const uint4*)(rp + NW_); \
    const uint4 x2 = *(const uint4*)(rp + 2 * NW_); \
    const uint4 x3 = *(const uint4*)(rp + 3 * NW_); \
    fa2(on0, acc0, x0.x ^ w[(KY)*3+0].x, x0.y ^ w[(KY)*3+0].y); \
    fa2(on0, acc0, x0.z ^ w[(KY)*3+0].z, x0.w ^ w[(KY)*3+0].w); \
    fa2(on1, acc1, x1.x ^ w[(KY)*3+0].x, x1.y ^ w[(KY)*3+0].y); \
    fa2(on1, acc1, x1.z ^ w[(KY)*3+0].z, x1.w ^ w[(KY)*3+0].w); \
    fa2(on0, acc0, x1.x ^ w[(KY)*3+1].x, x1.y ^ w[(KY)*3+1].y); \
    fa2(on0, acc0, x1.z ^ w[(KY)*3+1].z, x1.w ^ w[(KY)*3+1].w); \
    fa2(on1, acc1, x2.x ^ w[(KY)*3+1].x, x2.y ^ w[(KY)*3+1].y); \
    fa2(on1, acc1, x2.z ^ w[(KY)*3+1].z, x2.w ^ w[(KY)*3+1].w); \
    fa2(on0, acc0, x2.x ^ w[(KY)*3+2].x, x2.y ^ w[(KY)*3+2].y); \
    fa2(on0, acc0, x2.z ^ w[(KY)*3+2].z, x2.w ^ w[(KY)*3+2].w); \
    fa2(on1, acc1, x3.x ^ w[(KY)*3+2].x, x3.y ^ w[(KY)*3+2].y); \
    fa2(on1, acc1, x3.z ^ w[(KY)*3+2].z, x3.w ^ w[(KY)*3+2].w); \
}

__global__ __launch_bounds__(256, 3)
void conv_pop_k(const u64* __restrict__ Xp,
                const u64* __restrict__ Wp,
                const int* __restrict__ corr,
                short* __restrict__ S,
                ull* __restrict__ sum, ull* __restrict__ sq)
{
    __shared__ u64 sx[3 * PW_ * NW_];     // 5568 B
    const int t     = threadIdx.x;
    const int half  = t & 1;
    const int half2 = half * 2;
    const int c     = blockIdx.z * 128 + (t >> 1);
    const int oy    = blockIdx.x;
    const int n     = blockIdx.y;

    uint4 w[9];
    #pragma unroll
    for (int tp = 0; tp < 9; ++tp)
        w[tp] = *(const uint4*)&Wp[((size_t)tp * C_ + c) * NW_ + half2];

    const int rt = (oy == 0) ? 0 : ((oy == H_ - 1) ? 2 : 1);
    const int cL = corr[(rt * 3 + 0) * C_ + c];
    const int cM = corr[(rt * 3 + 1) * C_ + c];
    const int cR = corr[(rt * 3 + 2) * C_ + c];

    {
        const ulonglong2* src = (const ulonglong2*)(Xp + (((size_t)n * PH_ + oy) * PW_) * NW_);
        ulonglong2* dst = (ulonglong2*)sx;
        for (int i = t; i < 3 * PW_ * NW_ / 2; i += 256) dst[i] = src[i];
    }
    __syncthreads();

    int ss = 0, qq = 0;
    const size_t rowbase = (((size_t)n * H_ + oy) * W_) * C_ + c;

    #pragma unroll 1
    for (int ox = 0; ox < W_; ox += 2) {
        u32 on0 = 0, on1 = 0;
        int acc0 = 0, acc1 = 0;
        PAIRS_KY(0)
        PAIRS_KY(1)
        PAIRS_KY(2)
        acc0 += __popc(on0);              // total ones among 36 XOR words, pixel ox
        acc1 += __popc(on1);              // pixel ox+1
        const unsigned p01 = (unsigned)acc0 | ((unsigned)acc1 << 16);
        const unsigned f01 = p01 + __shfl_xor_sync(0xffffffffu, p01, 1);
        const int gx = ox + half;
        const int f  = half ? (int)(f01 >> 16) : (int)(f01 & 0xffffu);
        const int cc = (gx == 0) ? cL : ((gx == W_ - 1) ? cR : cM);
        const int sv = 2304 - 2 * f - cc;
        S[rowbase + (size_t)gx * C_] = (short)sv;
        ss += sv;
        qq += sv * sv;
    }
    atomicAdd(&sum[c], (ull)(long long)ss);
    atomicAdd(&sq[c],  (ull)(long long)qq);
}

// ============================ bn / thresh / final ============================
__global__ void bnparams_k(const ull* __restrict__ sum, const ull* __restrict__ sq,
                           const float* __restrict__ gamma, const float* __restrict__ beta,
                           float* __restrict__ a, float* __restrict__ b) {
    int c = threadIdx.x;
    const double M = (double)M_CNT_;
    double mS = (double)(long long)sum[c] / M;
    double vS = (double)(long long)sq[c] / M - mS * mS;
    double m = 0.5 * mS;
    double v = 0.25 * vS;
    double r = 1.0 / sqrt(v + 1e-5);
    double g = (double)gamma[c];
    a[c] = (float)(0.5 * r * g);
    b[c] = (float)((double)beta[c] - m * r * g);
}

__global__ void thresh_ballot_k(const short* __restrict__ S,
                                const float* __restrict__ a, const float* __restrict__ b,
                                u64* __restrict__ Xp2) {
    int c = threadIdx.x;
    int py = blockIdx.x, n = blockIdx.y;
    int warp = c >> 5, lane = c & 31;
    float av = a[c], bv = b[c];
    bool rowv = (py >= 1 && py <= H_);
    for (int px = 0; px < PW_; ++px) {
        unsigned bit = 0u;
        if (rowv && px >= 1 && px <= W_) {
            int v = S[(((size_t)n * H_ + (py - 1)) * W_ + (px - 1)) * C_ + c];
            bit = (av * (float)v + bv > 0.0f) ? 1u : 0u;
        }
        unsigned m = __ballot_sync(0xffffffffu, bit);
        if (lane == 0)
            ((unsigned*)(Xp2 + (((size_t)n * PH_ + py) * PW_ + px) * NW_))[warp] = m;
    }
}

__global__ __launch_bounds__(256)
void final_k(const short* __restrict__ S2,
             const float* __restrict__ a, const float* __restrict__ b,
             const float* __restrict__ x, float* __restrict__ out) {
    __shared__ short tile[32][33];
    int n = blockIdx.z, pt = blockIdx.x, ct = blockIdx.y;
    int tx = threadIdx.x, ty = threadIdx.y;
    #pragma unroll
    for (int i = 0; i < 4; ++i) {
        int rl = ty + i * 8;
        tile[rl][tx] = S2[((size_t)n * PIX_ + pt * 32 + rl) * C_ + ct * 32 + tx];
    }
    __syncthreads();
    int p = pt * 32 + tx;
    int py = p / W_, px = p % W_;
    #pragma unroll
    for (int i = 0; i < 4; ++i) {
        int cl = ty + i * 8;
        int cc = ct * 32 + cl;
        size_t oi = (((size_t)n * C_ + cc) * H_ + py) * W_ + px;
        float v = a[cc] * (float)tile[tx][cl] + b[cc] + x[oi];
        out[oi] = fminf(1.0f, fmaxf(-1.0f, v));
    }
}

// ============================ launch ============================
extern "C" void kernel_launch(void* const* d_in, const int* in_sizes, int n_in,
                              void* d_out, int out_size) {
    const float* x  = (const float*)d_in[0];
    const float* w1 = (const float*)d_in[1];
    const float* g1 = (const float*)d_in[2];
    const float* b1 = (const float*)d_in[3];
    const float* w2 = (const float*)d_in[4];
    const float* g2 = (const float*)d_in[5];
    const float* b2 = (const float*)d_in[6];
    float* out = (float*)d_out;

    void *pX1, *pX2, *pW1, *pW2, *pc1, *pc2, *pS1, *pS2;
    void *psum1, *psq1, *psum2, *psq2, *pa1, *pb1, *pa2, *pb2;
    cudaGetSymbolAddress(&pX1, g_Xp1);  cudaGetSymbolAddress(&pX2, g_Xp2);
    cudaGetSymbolAddress(&pW1, g_Wp1);  cudaGetSymbolAddress(&pW2, g_Wp2);
    cudaGetSymbolAddress(&pc1, g_c1);   cudaGetSymbolAddress(&pc2, g_c2);
    cudaGetSymbolAddress(&pS1, g_S1);   cudaGetSymbolAddress(&pS2, g_S2);
    cudaGetSymbolAddress(&psum1, g_sum1); cudaGetSymbolAddress(&psq1, g_sq1);
    cudaGetSymbolAddress(&psum2, g_sum2); cudaGetSymbolAddress(&psq2, g_sq2);
    cudaGetSymbolAddress(&pa1, g_a1);   cudaGetSymbolAddress(&pb1, g_b1);
    cudaGetSymbolAddress(&pa2, g_a2);   cudaGetSymbolAddress(&pb2, g_b2);

    // launch order keeps conv1 as launch #3 (the one ncu profiles)
    pack_w_k<<<9, 256>>>(w1, (u64*)pW1, 1);                         // #0 (zeros stats too)
    corr_w_k<<<1, 256>>>((const u64*)pW1, (int*)pc1);               // #1
    pack_x_k<<<dim3(PH_, N_), dim3(PW_, NW_)>>>(x, (u64*)pX1);      // #2
    conv_pop_k<<<dim3(H_, N_, 2), 256>>>((const u64*)pX1, (const u64*)pW1,   // #3
                                         (const int*)pc1, (short*)pS1,
                                         (ull*)psum1, (ull*)psq1);
    pack_w_k<<<9, 256>>>(w2, (u64*)pW2, 0);                         // #4
    corr_w_k<<<1, 256>>>((const u64*)pW2, (int*)pc2);               // #5
    bnparams_k<<<1, 256>>>((const ull*)psum1, (const ull*)psq1, g1, b1,
                           (float*)pa1, (float*)pb1);               // #6
    thresh_ballot_k<<<dim3(PH_, N_), 256>>>((const short*)pS1,
        (const float*)pa1, (const float*)pb1, (u64*)pX2);           // #7
    conv_pop_k<<<dim3(H_, N_, 2), 256>>>((const u64*)pX2, (const u64*)pW2,   // #8
                                         (const int*)pc2, (short*)pS2,
                                         (ull*)psum2, (ull*)psq2);
    bnparams_k<<<1, 256>>>((const ull*)psum2, (const ull*)psq2, g2, b2,
                           (float*)pa2, (float*)pb2);               // #9
    final_k<<<dim3(PIX_ / 32, 8, N_), dim3(32, 8)>>>(
        (const short*)pS2, (const float*)pa2, (const float*)pb2, x, out);   // #10
}

// round 11
// speedup vs baseline: 1.4630x; 1.0344x over previous
#include <cuda_runtime.h>
#include <cstdint>

typedef unsigned long long u64;
typedef unsigned long long ull;
typedef unsigned int u32;

// ============================ problem constants ============================
#define N_   32
#define C_   256
#define H_   56
#define W_   56
#define PH_  58
#define PW_  58
#define PIX_ (H_*W_)                 // 3136
#define M_CNT_ (N_*PIX_)             // 100352
#define NW_  4                       // u64 words per pixel (256 ch)
#define HALFW_ 28                    // half-row width
#define SLAB_ 30                     // halo-extended half-row cols

// ============================ device scratch ============================
__device__ __align__(16) u64 g_Xp1[(size_t)N_*PH_*PW_*NW_];
__device__ __align__(16) u64 g_Xp2[(size_t)N_*PH_*PW_*NW_];
__device__ __align__(16) u64 g_Wp1[9*C_*NW_];
__device__ __align__(16) u64 g_Wp2[9*C_*NW_];
__device__ int  g_c1[9*C_];
__device__ int  g_c2[9*C_];
__device__ __align__(16) short g_S1[(size_t)M_CNT_*C_];
__device__ __align__(16) short g_S2[(size_t)M_CNT_*C_];
__device__ ull g_sum1[C_], g_sq1[C_], g_sum2[C_], g_sq2[C_];
__device__ float g_a1[C_], g_b1[C_], g_a2[C_], g_b2[C_];

// ============================ setup kernels ============================
// packs BOTH weight tensors: blocks 0..8 -> w1 taps, 9..17 -> w2 taps
__global__ void pack_w_k(const float* __restrict__ w1, const float* __restrict__ w2,
                         u64* __restrict__ Wp1, u64* __restrict__ Wp2) {
    int blk = blockIdx.x, c = threadIdx.x;
    if (blk == 0) {
        g_sum1[c] = 0ull; g_sq1[c] = 0ull; g_sum2[c] = 0ull; g_sq2[c] = 0ull;
    }
    const float* w = (blk < 9) ? w1 : w2;
    u64* Wp = (blk < 9) ? Wp1 : Wp2;
    int t = (blk < 9) ? blk : blk - 9;
    int ky = t / 3, kx = t % 3;
    #pragma unroll
    for (int j = 0; j < NW_; ++j) {
        u64 bits = 0ull;
        #pragma unroll 4
        for (int cl = 0; cl < 64; ++cl) {
            float v = w[(((size_t)c * C_ + (j * 64 + cl)) * 3 + ky) * 3 + kx];
            bits |= (u64)(v > 0.0f) << cl;
        }
        Wp[((size_t)t * C_ + c) * NW_ + j] = bits;
    }
}

// border corrections for both convs: block 0 -> (Wp1,c1), block 1 -> (Wp2,c2)
__global__ void corr_w_k() {
    const u64* Wp = blockIdx.x ? g_Wp2 : g_Wp1;
    int* corr     = blockIdx.x ? g_c2  : g_c1;
    int c = threadIdx.x;
    int pc[9];
    #pragma unroll
    for (int t = 0; t < 9; ++t) {
        int s = 0;
        #pragma unroll
        for (int j = 0; j < NW_; ++j) s += __popcll(Wp[((size_t)t * C_ + c) * NW_ + j]);
        pc[t] = s;
    }
    for (int type = 0; type < 9; ++type) {
        int rt = type / 3, ct = type % 3;
        int s = 0;
        #pragma unroll
        for (int ky = 0; ky < 3; ++ky)
            #pragma unroll
            for (int kx = 0; kx < 3; ++kx) {
                bool rinv = (rt == 0 && ky == 0) || (rt == 2 && ky == 2);
                bool cinv = (ct == 0 && kx == 0) || (ct == 2 && kx == 2);
                if (rinv || cinv) s += 256 - 2 * pc[ky * 3 + kx];
            }
        corr[type * C_ + c] = s;
    }
}

__global__ void pack_x_k(const float* __restrict__ x, u64* __restrict__ Xp) {
    int px = threadIdx.x, j = threadIdx.y;
    int py = blockIdx.x, n = blockIdx.y;
    size_t oidx = (((size_t)n * PH_ + py) * PW_ + px) * NW_ + j;
    if (px == 0 || px == PW_ - 1 || py == 0 || py == PH_ - 1) { Xp[oidx] = 0ull; return; }
    const float* xp = x + (((size_t)n * C_ + j * 64) * H_ + (py - 1)) * W_ + (px - 1);
    u64 bits = 0ull;
    #pragma unroll 8
    for (int cl = 0; cl < 64; ++cl)
        bits |= (u64)(xp[(size_t)cl * PIX_] > 0.0f) << cl;
    Xp[oidx] = bits;
}

// ============================ shallow CSA primitives ============================
__device__ __forceinline__ u32 xor3(u32 a, u32 b, u32 c) {
    u32 d; asm("lop3.b32 %0,%1,%2,%3,0x96;" : "=r"(d) : "r"(a), "r"(b), "r"(c)); return d;
}
__device__ __forceinline__ u32 maj3(u32 a, u32 b, u32 c) {
    u32 d; asm("lop3.b32 %0,%1,%2,%3,0xE8;" : "=r"(d) : "r"(a), "r"(b), "r"(c)); return d;
}
__device__ __forceinline__ void fa2(u32& on, int& acc, u32 a, u32 b) {
    u32 c1 = maj3(on, a, b);
    on = xor3(on, a, b);
    int pc = __popc(c1);
    asm("mad.lo.s32 %0, %1, 2, %0;" : "+r"(acc) : "r"(pc));
}

// ============================ hot kernel: balanced-pipe XNOR conv ============================
// CTA = half row (28 px), 30-col smem slab; thread = (cout, half-of-256-cin).
#define PAIRS_KY(KY) { \
    const u64* rp = &sx[((KY) * SLAB_ + ox) * NW_ + half2]; \
    const uint4 x0 = *(const uint4*)(rp); \
    const uint4 x1 = *(const uint4*)(rp + NW_); \
    const uint4 x2 = *(const uint4*)(rp + 2 * NW_); \
    const uint4 x3 = *(const uint4*)(rp + 3 * NW_); \
    fa2(on0, acc0, x0.x ^ w[(KY)*3+0].x, x0.y ^ w[(KY)*3+0].y); \
    fa2(on0, acc0, x0.z ^ w[(KY)*3+0].z, x0.w ^ w[(KY)*3+0].w); \
    fa2(on1, acc1, x1.x ^ w[(KY)*3+0].x, x1.y ^ w[(KY)*3+0].y); \
    fa2(on1, acc1, x1.z ^ w[(KY)*3+0].z, x1.w ^ w[(KY)*3+0].w); \
    fa2(on0, acc0, x1.x ^ w[(KY)*3+1].x, x1.y ^ w[(KY)*3+1].y); \
    fa2(on0, acc0, x1.z ^ w[(KY)*3+1].z, x1.w ^ w[(KY)*3+1].w); \
    fa2(on1, acc1, x2.x ^ w[(KY)*3+1].x, x2.y ^ w[(KY)*3+1].y); \
    fa2(on1, acc1, x2.z ^ w[(KY)*3+1].z, x2.w ^ w[(KY)*3+1].w); \
    fa2(on0, acc0, x2.x ^ w[(KY)*3+2].x, x2.y ^ w[(KY)*3+2].y); \
    fa2(on0, acc0, x2.z ^ w[(KY)*3+2].z, x2.w ^ w[(KY)*3+2].w); \
    fa2(on1, acc1, x3.x ^ w[(KY)*3+2].x, x3.y ^ w[(KY)*3+2].y); \
    fa2(on1, acc1, x3.z ^ w[(KY)*3+2].z, x3.w ^ w[(KY)*3+2].w); \
}

__global__ __launch_bounds__(256, 3)
void conv_pop_k(const u64* __restrict__ Xp,
                const u64* __restrict__ Wp,
                const int* __restrict__ corr,
                short* __restrict__ S,
                ull* __restrict__ sum, ull* __restrict__ sq)
{
    __shared__ u64 sx[3 * SLAB_ * NW_];   // 2880 B
    const int t     = threadIdx.x;
    const int half  = t & 1;
    const int half2 = half * 2;
    const int c     = blockIdx.z * 128 + (t >> 1);
    const int oy    = blockIdx.x >> 1;
    const int xh    = blockIdx.x & 1;     // half-row index
    const int n     = blockIdx.y;
    const int cbase = xh * HALFW_;        // 0 or 28 (global first output px of slab)

    uint4 w[9];
    #pragma unroll
    for (int tp = 0; tp < 9; ++tp)
        w[tp] = *(const uint4*)&Wp[((size_t)tp * C_ + c) * NW_ + half2];

    const int rt = (oy == 0) ? 0 : ((oy == H_ - 1) ? 2 : 1);
    const int cL = corr[(rt * 3 + 0) * C_ + c];
    const int cM = corr[(rt * 3 + 1) * C_ + c];
    const int cR = corr[(rt * 3 + 2) * C_ + c];

    // load 3 padded rows x 30 cols into smem (each col = 4 u64 = 2 ulonglong2)
    {
        ulonglong2* dst = (ulonglong2*)sx;
        // 3 rows * 30 cols * 2 = 180 ulonglong2
        for (int i = t; i < 3 * SLAB_ * 2; i += 256) {
            int r = i / (SLAB_ * 2), rem = i - r * (SLAB_ * 2);
            const ulonglong2* src = (const ulonglong2*)
                (Xp + (((size_t)n * PH_ + oy + r) * PW_ + cbase) * NW_);
            dst[r * SLAB_ * 2 + rem] = src[rem];
        }
    }
    __syncthreads();

    int ss = 0, qq = 0;
    const size_t rowbase = (((size_t)n * H_ + oy) * W_) * C_ + c;

    #pragma unroll 1
    for (int ox = 0; ox < HALFW_; ox += 2) {
        u32 on0 = 0, on1 = 0;
        int acc0 = 0, acc1 = 0;
        PAIRS_KY(0)
        PAIRS_KY(1)
        PAIRS_KY(2)
        acc0 += __popc(on0);
        acc1 += __popc(on1);
        const unsigned p01 = (unsigned)acc0 | ((unsigned)acc1 << 16);
        const unsigned f01 = p01 + __shfl_xor_sync(0xffffffffu, p01, 1);
        const int gx = cbase + ox + half;
        const int f  = half ? (int)(f01 >> 16) : (int)(f01 & 0xffffu);
        const int cc = (gx == 0) ? cL : ((gx == W_ - 1) ? cR : cM);
        const int sv = 2304 - 2 * f - cc;
        S[rowbase + (size_t)gx * C_] = (short)sv;
        ss += sv;
        qq += sv * sv;
    }
    atomicAdd(&sum[c], (ull)(long long)ss);
    atomicAdd(&sq[c],  (ull)(long long)qq);
}

// ============================ bn / thresh / final ============================
__global__ void bnparams_k(const ull* __restrict__ sum, const ull* __restrict__ sq,
                           const float* __restrict__ gamma, const float* __restrict__ beta,
                           float* __restrict__ a, float* __restrict__ b) {
    int c = threadIdx.x;
    const double M = (double)M_CNT_;
    double mS = (double)(long long)sum[c] / M;
    double vS = (double)(long long)sq[c] / M - mS * mS;
    double m = 0.5 * mS;
    double v = 0.25 * vS;
    double r = 1.0 / sqrt(v + 1e-5);
    double g = (double)gamma[c];
    a[c] = (float)(0.5 * r * g);
    b[c] = (float)((double)beta[c] - m * r * g);
}

__global__ void thresh_ballot_k(const short* __restrict__ S,
                                const float* __restrict__ a, const float* __restrict__ b,
                                u64* __restrict__ Xp2) {
    int c = threadIdx.x;
    int py = blockIdx.x, n = blockIdx.y;
    int warp = c >> 5, lane = c & 31;
    float av = a[c], bv = b[c];
    bool rowv = (py >= 1 && py <= H_);
    #pragma unroll 4
    for (int px = 0; px < PW_; ++px) {
        unsigned bit = 0u;
        if (rowv && px >= 1 && px <= W_) {
            int v = S[(((size_t)n * H_ + (py - 1)) * W_ + (px - 1)) * C_ + c];
            bit = (av * (float)v + bv > 0.0f) ? 1u : 0u;
        }
        unsigned m = __ballot_sync(0xffffffffu, bit);
        if (lane == 0)
            ((unsigned*)(Xp2 + (((size_t)n * PH_ + py) * PW_ + px) * NW_))[warp] = m;
    }
}

__global__ __launch_bounds__(256)
void final_k(const short* __restrict__ S2,
             const float* __restrict__ a, const float* __restrict__ b,
             const float* __restrict__ x, float* __restrict__ out) {
    __shared__ short tile[32][33];
    int n = blockIdx.z, pt = blockIdx.x, ct = blockIdx.y;
    int tx = threadIdx.x, ty = threadIdx.y;
    #pragma unroll
    for (int i = 0; i < 4; ++i) {
        int rl = ty + i * 8;
        tile[rl][tx] = S2[((size_t)n * PIX_ + pt * 32 + rl) * C_ + ct * 32 + tx];
    }
    __syncthreads();
    int p = pt * 32 + tx;
    int py = p / W_, px = p % W_;
    #pragma unroll
    for (int i = 0; i < 4; ++i) {
        int cl = ty + i * 8;
        int cc = ct * 32 + cl;
        size_t oi = (((size_t)n * C_ + cc) * H_ + py) * W_ + px;
        float v = a[cc] * (float)tile[tx][cl] + b[cc] + x[oi];
        out[oi] = fminf(1.0f, fmaxf(-1.0f, v));
    }
}

// ============================ launch ============================
extern "C" void kernel_launch(void* const* d_in, const int* in_sizes, int n_in,
                              void* d_out, int out_size) {
    const float* x  = (const float*)d_in[0];
    const float* w1 = (const float*)d_in[1];
    const float* g1 = (const float*)d_in[2];
    const float* b1 = (const float*)d_in[3];
    const float* w2 = (const float*)d_in[4];
    const float* g2 = (const float*)d_in[5];
    const float* b2 = (const float*)d_in[6];
    float* out = (float*)d_out;

    void *pX1, *pX2, *pW1, *pW2, *pc1, *pc2, *pS1, *pS2;
    void *psum1, *psq1, *psum2, *psq2, *pa1, *pb1, *pa2, *pb2;
    cudaGetSymbolAddress(&pX1, g_Xp1);  cudaGetSymbolAddress(&pX2, g_Xp2);
    cudaGetSymbolAddress(&pW1, g_Wp1);  cudaGetSymbolAddress(&pW2, g_Wp2);
    cudaGetSymbolAddress(&pc1, g_c1);   cudaGetSymbolAddress(&pc2, g_c2);
    cudaGetSymbolAddress(&pS1, g_S1);   cudaGetSymbolAddress(&pS2, g_S2);
    cudaGetSymbolAddress(&psum1, g_sum1); cudaGetSymbolAddress(&psq1, g_sq1);
    cudaGetSymbolAddress(&psum2, g_sum2); cudaGetSymbolAddress(&psq2, g_sq2);
    cudaGetSymbolAddress(&pa1, g_a1);   cudaGetSymbolAddress(&pb1, g_b1);
    cudaGetSymbolAddress(&pa2, g_a2);   cudaGetSymbolAddress(&pb2, g_b2);

    // conv1 stays launch #3 (the one ncu profiles)
    pack_w_k<<<18, 256>>>(w1, w2, (u64*)pW1, (u64*)pW2);            // #0 (zeros stats)
    corr_w_k<<<2, 256>>>();                                          // #1
    pack_x_k<<<dim3(PH_, N_), dim3(PW_, NW_)>>>(x, (u64*)pX1);       // #2
    conv_pop_k<<<dim3(H_ * 2, N_, 2), 256>>>((const u64*)pX1, (const u64*)pW1,  // #3
                                             (const int*)pc1, (short*)pS1,
                                             (ull*)psum1, (ull*)psq1);
    bnparams_k<<<1, 256>>>((const ull*)psum1, (const ull*)psq1, g1, b1,
                           (float*)pa1, (float*)pb1);                // #4
    thresh_ballot_k<<<dim3(PH_, N_), 256>>>((const short*)pS1,
        (const float*)pa1, (const float*)pb1, (u64*)pX2);            // #5
    conv_pop_k<<<dim3(H_ * 2, N_, 2), 256>>>((const u64*)pX2, (const u64*)pW2,  // #6
                                             (const int*)pc2, (short*)pS2,
                                             (ull*)psum2, (ull*)psq2);
    bnparams_k<<<1, 256>>>((const ull*)psum2, (const ull*)psq2, g2, b2,
                           (float*)pa2, (float*)pb2);                // #7
    final_k<<<dim3(PIX_ / 32, 8, N_), dim3(32, 8)>>>(
        (const short*)pS2, (const float*)pa2, (const float*)pb2, x, out);       // #8
}